// round 2
// baseline (speedup 1.0000x reference)
#include <cuda_runtime.h>
#include <math.h>
#include <stdint.h>

#define B_  8
#define N_  8192
#define C_  64
#define S_  2048
#define KNB 32
#define PTS (S_*KNB)

__device__ float  g_featT[(size_t)B_*N_*C_];
__device__ float  g_centers[B_*3*S_];
__device__ int    g_nidx[B_*S_*KNB];
__device__ float  g_bufA[(size_t)B_*128*PTS];
__device__ float  g_bufB[(size_t)B_*128*PTS];
__device__ double g_csum[2048];
__device__ double g_csq [2048];

/* ------------ transpose features [b][c][n] -> [b][n][c] ------------ */
__global__ void k_transpose(const float* __restrict__ f) {
    __shared__ float t[32][33];
    int b = blockIdx.z;
    int nb = blockIdx.x * 32, cb = blockIdx.y * 32;
    int tx = threadIdx.x, ty = threadIdx.y;
#pragma unroll
    for (int j = 0; j < 32; j += 8)
        t[ty + j][tx] = f[((size_t)b*C_ + cb + ty + j)*N_ + nb + tx];
    __syncthreads();
#pragma unroll
    for (int j = 0; j < 32; j += 8)
        g_featT[((size_t)b*N_ + nb + ty + j)*C_ + cb + tx] = t[tx][ty + j];
}

/* ------------ FPS: one block per batch ------------ */
#define FPS_SMEM ((3*N_ + 64 + 4)*4)
__global__ void __launch_bounds__(1024, 1) k_fps(const float* __restrict__ coords) {
    extern __shared__ float sm[];
    float* sx = sm; float* sy = sm + N_; float* sz = sm + 2*N_;
    unsigned long long* wb = (unsigned long long*)(sm + 3*N_);
    float* lastp = sm + 3*N_ + 64;
    int b = blockIdx.x, tid = threadIdx.x;
    const float* cb = coords + (size_t)b*3*N_;

    float px[8], py[8], pz[8], mind[8];
#pragma unroll
    for (int j = 0; j < 8; j++) {
        int n = j*1024 + tid;
        px[j] = cb[n]; py[j] = cb[N_ + n]; pz[j] = cb[2*N_ + n];
        sx[n] = px[j]; sy[n] = py[j]; sz[n] = pz[j];
        mind[j] = 1e10f;
    }
    if (tid == 0) {
        lastp[0] = cb[0]; lastp[1] = cb[N_]; lastp[2] = cb[2*N_];
        g_centers[(b*3+0)*S_] = lastp[0];
        g_centers[(b*3+1)*S_] = lastp[1];
        g_centers[(b*3+2)*S_] = lastp[2];
    }
    __syncthreads();

    int lane = tid & 31, wid = tid >> 5;
    for (int step = 1; step < S_; ++step) {
        float lx = lastp[0], ly = lastp[1], lz = lastp[2];
        float bd = -1.0f; int bn = 0;
#pragma unroll
        for (int j = 0; j < 8; j++) {
            float dx = __fsub_rn(px[j], lx);
            float dy = __fsub_rn(py[j], ly);
            float dz = __fsub_rn(pz[j], lz);
            float d  = __fadd_rn(__fadd_rn(__fmul_rn(dx,dx), __fmul_rn(dy,dy)), __fmul_rn(dz,dz));
            float m  = fminf(mind[j], d);
            mind[j] = m;
            if (m > bd) { bd = m; bn = j*1024 + tid; }
        }
        unsigned long long pk =
            ((unsigned long long)__float_as_uint(bd) << 32) |
            (unsigned)(0xFFFFFFFFu - (unsigned)bn);
#pragma unroll
        for (int off = 16; off; off >>= 1) {
            unsigned long long o = __shfl_xor_sync(0xffffffffu, pk, off);
            if (o > pk) pk = o;
        }
        if (lane == 0) wb[wid] = pk;
        __syncthreads();
        if (wid == 0) {
            unsigned long long v = wb[lane];
#pragma unroll
            for (int off = 16; off; off >>= 1) {
                unsigned long long o = __shfl_xor_sync(0xffffffffu, v, off);
                if (o > v) v = o;
            }
            if (lane == 0) {
                int widx = (int)(0xFFFFFFFFu - (unsigned)v);
                float wx = sx[widx], wy = sy[widx], wz = sz[widx];
                lastp[0] = wx; lastp[1] = wy; lastp[2] = wz;
                g_centers[(b*3+0)*S_ + step] = wx;
                g_centers[(b*3+1)*S_ + step] = wy;
                g_centers[(b*3+2)*S_ + step] = wz;
            }
        }
        __syncthreads();
    }
}

/* ------------ ball query: warp per center ------------ */
#define BALL_SMEM (3*N_*4)
__global__ void __launch_bounds__(256) k_ball(const float* __restrict__ coords) {
    extern __shared__ float sm[];
    float* sx = sm; float* sy = sm + N_; float* sz = sm + 2*N_;
    int blk = blockIdx.x;
    int b = blk >> 5, part = blk & 31;
    int tid = threadIdx.x;
    const float* cb = coords + (size_t)b*3*N_;
    for (int n = tid; n < N_; n += 256) {
        sx[n] = cb[n]; sy[n] = cb[N_ + n]; sz[n] = cb[2*N_ + n];
    }
    __syncthreads();
    int w = tid >> 5, lane = tid & 31;
    for (int cc = 0; cc < 8; cc++) {
        int s = part*64 + w*8 + cc;
        float cx = g_centers[(b*3+0)*S_ + s];
        float cy = g_centers[(b*3+1)*S_ + s];
        float cz = g_centers[(b*3+2)*S_ + s];
        float cn = __fadd_rn(__fadd_rn(__fmul_rn(cx,cx), __fmul_rn(cy,cy)), __fmul_rn(cz,cz));
        int found = 0, firstn = 0;
        int* op = &g_nidx[((size_t)b*S_ + s)*KNB];
        for (int base = 0; base < N_; base += 32) {
            int n = base + lane;
            float x = sx[n], y = sy[n], z = sz[n];
            float pn = __fadd_rn(__fadd_rn(__fmul_rn(x,x), __fmul_rn(y,y)), __fmul_rn(z,z));
            float cp = __fadd_rn(__fadd_rn(__fmul_rn(cx,x), __fmul_rn(cy,y)), __fmul_rn(cz,z));
            float d2 = __fsub_rn(__fadd_rn(cn, pn), __fmul_rn(2.0f, cp));
            bool hit = d2 < 0.0625f;
            unsigned bal = __ballot_sync(0xffffffffu, hit);
            if (bal) {
                if (found == 0) firstn = base + __ffs(bal) - 1;
                int slot = found + __popc(bal & ((1u << lane) - 1u));
                if (hit && slot < KNB) op[slot] = n;
                found += __popc(bal);
                if (found >= KNB) break;
            }
        }
        if (found < KNB) {
            int fill = (found > 0) ? firstn : 0;
            for (int sl = found + lane; sl < KNB; sl += 32) op[sl] = fill;
        }
    }
}

/* ------------ conv0: gather + (67->64) + bias -> bufA ------------ */
#define CONV0_SMEM ((64*68 + 64 + 68*128)*4)
__global__ void __launch_bounds__(128) k_conv0(const float* __restrict__ coords,
                                               const float* __restrict__ w0,
                                               const float* __restrict__ b0) {
    extern __shared__ float sm[];
    float* ws = sm;                 /* [64][68] */
    float* bs = ws + 64*68;
    float* xs = bs + 64;            /* [68][128] */
    int tid = threadIdx.x;
    int b = blockIdx.x >> 9;
    int p = (blockIdx.x & 511)*128 + tid;

    for (int k2 = tid; k2 < 64*68; k2 += 128) {
        int o = k2 / 68, i = k2 - o*68;
        ws[k2] = (i < 67) ? w0[o*67 + i] : 0.0f;
    }
    if (tid < 64) bs[tid] = b0[tid];

    int s = p >> 5;
    int n = g_nidx[((size_t)b*S_ + s)*KNB + (p & 31)];
    const float* cb = coords + (size_t)b*3*N_;
    xs[0*128 + tid] = __fsub_rn(cb[n],        g_centers[(b*3+0)*S_ + s]);
    xs[1*128 + tid] = __fsub_rn(cb[N_ + n],   g_centers[(b*3+1)*S_ + s]);
    xs[2*128 + tid] = __fsub_rn(cb[2*N_ + n], g_centers[(b*3+2)*S_ + s]);
    const float4* fp = (const float4*)(g_featT + ((size_t)b*N_ + n)*C_);
#pragma unroll
    for (int q = 0; q < 16; q++) {
        float4 v = fp[q]; int ib = 3 + 4*q;
        xs[(ib+0)*128 + tid] = v.x; xs[(ib+1)*128 + tid] = v.y;
        xs[(ib+2)*128 + tid] = v.z; xs[(ib+3)*128 + tid] = v.w;
    }
    xs[67*128 + tid] = 0.0f;
    __syncthreads();

    float acc[64];
#pragma unroll
    for (int o = 0; o < 64; o++) acc[o] = bs[o];
#pragma unroll 1
    for (int i = 0; i < 68; i += 4) {
        float x0 = xs[(i+0)*128 + tid], x1 = xs[(i+1)*128 + tid];
        float x2 = xs[(i+2)*128 + tid], x3 = xs[(i+3)*128 + tid];
#pragma unroll
        for (int o = 0; o < 64; o++) {
            float4 w = *reinterpret_cast<const float4*>(ws + o*68 + i);
            acc[o] = fmaf(w.x, x0, acc[o]);
            acc[o] = fmaf(w.y, x1, acc[o]);
            acc[o] = fmaf(w.z, x2, acc[o]);
            acc[o] = fmaf(w.w, x3, acc[o]);
        }
    }
    float* yb = g_bufA + ((size_t)b*64)*PTS + p;
#pragma unroll
    for (int o = 0; o < 64; o++) yb[(size_t)o*PTS] = acc[o];
}

/* ------------ per-(b,c) stats: deterministic two-stage ------------ */
template<int COUT, bool SRC_A>
__global__ void __launch_bounds__(256) k_stats(int off) {
    const float* y = SRC_A ? g_bufA : g_bufB;
    int bc = blockIdx.x;
    const float4* p4 = (const float4*)(y + (size_t)bc*PTS);
    float s = 0.0f, q = 0.0f;
    for (int i = threadIdx.x; i < PTS/4; i += 256) {
        float4 v = p4[i];
        s += v.x + v.y + v.z + v.w;
        q += v.x*v.x + v.y*v.y + v.z*v.z + v.w*v.w;
    }
    double ds = (double)s, dq = (double)q;
    int lane = threadIdx.x & 31, w = threadIdx.x >> 5;
#pragma unroll
    for (int o = 16; o; o >>= 1) {
        ds += __shfl_xor_sync(0xffffffffu, ds, o);
        dq += __shfl_xor_sync(0xffffffffu, dq, o);
    }
    __shared__ double sh[16];
    if (lane == 0) { sh[w] = ds; sh[8 + w] = dq; }
    __syncthreads();
    if (threadIdx.x == 0) {
        double S = 0.0, Q = 0.0;
#pragma unroll
        for (int i = 0; i < 8; i++) { S += sh[i]; Q += sh[8 + i]; }
        g_csum[off + bc] = S; g_csq[off + bc] = Q;
    }
}

/* ------------ convN: GN(prev) + SiLU + (64->COUT) + bias ------------ */
template<int COUT, bool IN_A>
__global__ void __launch_bounds__(128) k_convN(const float* __restrict__ w,
                                               const float* __restrict__ bb,
                                               const float* __restrict__ gamma,
                                               const float* __restrict__ beta,
                                               int off, double inv_cnt) {
    extern __shared__ float sm[];
    float* ws = sm;                 /* [COUT][64] */
    float* bs = ws + COUT*64;
    float* al = bs + COUT;
    float* bt = al + 64;
    float* xs = bt + 64;            /* [64][128] */
    int tid = threadIdx.x;
    int b = blockIdx.x >> 9;
    int p = (blockIdx.x & 511)*128 + tid;
    const float* yin  = IN_A ? g_bufA : g_bufB;
    float*       yout = IN_A ? g_bufB : g_bufA;

    for (int k2 = tid; k2 < COUT*64; k2 += 128) ws[k2] = w[k2];
    if (tid < COUT) bs[tid] = bb[tid];
    if (tid < 64) {
        int g = tid >> 3;
        double ms = 0.0, qs = 0.0;
#pragma unroll
        for (int cc = 0; cc < 8; cc++) {
            ms += g_csum[off + b*64 + g*8 + cc];
            qs += g_csq [off + b*64 + g*8 + cc];
        }
        double mu  = ms * inv_cnt;
        double var = qs * inv_cnt - mu*mu;
        float rstd = (float)rsqrt(var + 1e-5);
        float a = gamma[tid] * rstd;
        al[tid] = a;
        bt[tid] = beta[tid] - (float)mu * a;
    }
    __syncthreads();

#pragma unroll 1
    for (int ci = 0; ci < 64; ci++) {
        float v  = yin[((size_t)b*64 + ci)*PTS + p];
        float xn = fmaf(v, al[ci], bt[ci]);
        float sg = __fdividef(1.0f, 1.0f + __expf(-xn));
        xs[ci*128 + tid] = xn * sg;
    }
    __syncthreads();

    float acc[COUT];
#pragma unroll
    for (int o = 0; o < COUT; o++) acc[o] = bs[o];
#pragma unroll 1
    for (int i = 0; i < 64; i += 4) {
        float x0 = xs[(i+0)*128 + tid], x1 = xs[(i+1)*128 + tid];
        float x2 = xs[(i+2)*128 + tid], x3 = xs[(i+3)*128 + tid];
#pragma unroll
        for (int o = 0; o < COUT; o++) {
            float4 wv = *reinterpret_cast<const float4*>(ws + o*64 + i);
            acc[o] = fmaf(wv.x, x0, acc[o]);
            acc[o] = fmaf(wv.y, x1, acc[o]);
            acc[o] = fmaf(wv.z, x2, acc[o]);
            acc[o] = fmaf(wv.w, x3, acc[o]);
        }
    }
    float* yb = yout + ((size_t)b*COUT)*PTS + p;
#pragma unroll
    for (int o = 0; o < COUT; o++) yb[(size_t)o*PTS] = acc[o];
}

/* ------------ final: GN + SiLU + max over K ------------ */
__global__ void __launch_bounds__(256) k_final(const float* __restrict__ gamma,
                                               const float* __restrict__ beta,
                                               float* __restrict__ out,
                                               int off, double inv_cnt) {
    int blk = blockIdx.x;
    int bc = blk >> 5;            /* b*128 + c */
    int chunk = blk & 31;
    int b = bc >> 7, c = bc & 127;
    __shared__ float s_a, s_b;
    if (threadIdx.x == 0) {
        int g = c >> 4;
        double ms = 0.0, qs = 0.0;
#pragma unroll
        for (int cc = 0; cc < 16; cc++) {
            ms += g_csum[off + b*128 + g*16 + cc];
            qs += g_csq [off + b*128 + g*16 + cc];
        }
        double mu  = ms * inv_cnt;
        double var = qs * inv_cnt - mu*mu;
        float rstd = (float)rsqrt(var + 1e-5);
        float a = gamma[c] * rstd;
        s_a = a;
        s_b = beta[c] - (float)mu * a;
    }
    __syncthreads();
    float a = s_a, bt = s_b;
    int w = threadIdx.x >> 5, lane = threadIdx.x & 31;
    const float* base = g_bufA + (size_t)bc*PTS;
#pragma unroll 1
    for (int j = 0; j < 8; j++) {
        int s = chunk*64 + w*8 + j;
        float v  = base[s*32 + lane];
        float xn = fmaf(v, a, bt);
        float sg = __fdividef(1.0f, 1.0f + __expf(-xn));
        float val = xn * sg;
#pragma unroll
        for (int o = 16; o; o >>= 1)
            val = fmaxf(val, __shfl_xor_sync(0xffffffffu, val, o));
        if (lane == 0) out[(size_t)bc*S_ + s] = val;
    }
}

extern "C" void kernel_launch(void* const* d_in, const int* in_sizes, int n_in,
                              void* d_out, int out_size) {
    const float* coords   = (const float*)d_in[0];
    const float* features = (const float*)d_in[1];
    const float* w0 = (const float*)d_in[2];
    const float* b0 = (const float*)d_in[3];
    const float* g0 = (const float*)d_in[4];
    const float* be0= (const float*)d_in[5];
    const float* w1 = (const float*)d_in[6];
    const float* b1 = (const float*)d_in[7];
    const float* g1 = (const float*)d_in[8];
    const float* be1= (const float*)d_in[9];
    const float* w2 = (const float*)d_in[10];
    const float* b2 = (const float*)d_in[11];
    const float* g2 = (const float*)d_in[12];
    const float* be2= (const float*)d_in[13];
    float* out = (float*)d_out;

    cudaFuncSetAttribute(k_fps,   cudaFuncAttributeMaxDynamicSharedMemorySize, FPS_SMEM);
    cudaFuncSetAttribute(k_ball,  cudaFuncAttributeMaxDynamicSharedMemorySize, BALL_SMEM);
    cudaFuncSetAttribute(k_conv0, cudaFuncAttributeMaxDynamicSharedMemorySize, CONV0_SMEM);
    cudaFuncSetAttribute(k_convN<64,true>,   cudaFuncAttributeMaxDynamicSharedMemorySize, (64*64+64+128+64*128)*4);
    cudaFuncSetAttribute(k_convN<128,false>, cudaFuncAttributeMaxDynamicSharedMemorySize, (128*64+128+128+64*128)*4);

    dim3 tg(N_/32, C_/32, B_);
    k_transpose<<<tg, dim3(32,8)>>>(features);
    k_fps<<<B_, 1024, FPS_SMEM>>>(coords);
    k_ball<<<B_*32, 256, BALL_SMEM>>>(coords);
    k_conv0<<<B_*512, 128, CONV0_SMEM>>>(coords, w0, b0);
    k_stats<64,true><<<B_*64, 256>>>(0);
    k_convN<64,true><<<B_*512, 128, (64*64+64+128+64*128)*4>>>(w1, b1, g0, be0, 0, 1.0/(8.0*PTS));
    k_stats<64,false><<<B_*64, 256>>>(512);
    k_convN<128,false><<<B_*512, 128, (128*64+128+128+64*128)*4>>>(w2, b2, g1, be1, 512, 1.0/(8.0*PTS));
    k_stats<128,true><<<B_*128, 256>>>(1024);
    k_final<<<B_*128*32, 256>>>(g2, be2, out, 1024, 1.0/(16.0*PTS));
}

// round 3
// speedup vs baseline: 1.1795x; 1.1795x over previous
#include <cuda_runtime.h>
#include <math.h>
#include <stdint.h>

#define B_  8
#define N_  8192
#define C_  64
#define S_  2048
#define KNB 32
#define PTS (S_*KNB)
typedef unsigned long long ull;

__device__ float  g_featT[(size_t)B_*N_*C_];
__device__ float  g_centers[B_*3*S_];
__device__ int    g_nidx[B_*S_*KNB];
__device__ float  g_bufA[(size_t)B_*128*PTS];
__device__ float  g_bufB[(size_t)B_*128*PTS];
__device__ double g_csum[2048];
__device__ double g_csq [2048];

__device__ __forceinline__ ull pk2(float lo, float hi) {
    ull r; asm("mov.b64 %0,{%1,%2};" : "=l"(r) : "f"(lo), "f"(hi)); return r;
}
__device__ __forceinline__ void upk2(ull v, float& lo, float& hi) {
    asm("mov.b64 {%0,%1},%2;" : "=f"(lo), "=f"(hi) : "l"(v));
}
__device__ __forceinline__ ull add2(ull a, ull b) {
    ull r; asm("add.rn.f32x2 %0,%1,%2;" : "=l"(r) : "l"(a), "l"(b)); return r;
}
__device__ __forceinline__ ull mul2(ull a, ull b) {
    ull r; asm("mul.rn.f32x2 %0,%1,%2;" : "=l"(r) : "l"(a), "l"(b)); return r;
}
__device__ __forceinline__ ull fma2(ull a, ull b, ull c) {
    ull r; asm("fma.rn.f32x2 %0,%1,%2,%3;" : "=l"(r) : "l"(a), "l"(b), "l"(c)); return r;
}
__device__ __forceinline__ unsigned redmin(unsigned v) {
    unsigned r; asm("redux.sync.min.u32 %0,%1,0xffffffff;" : "=r"(r) : "r"(v)); return r;
}

/* ------------ transpose features [b][c][n] -> [b][n][c] ------------ */
__global__ void k_transpose(const float* __restrict__ f) {
    __shared__ float t[32][33];
    int b = blockIdx.z;
    int nb = blockIdx.x * 32, cb = blockIdx.y * 32;
    int tx = threadIdx.x, ty = threadIdx.y;
#pragma unroll
    for (int j = 0; j < 32; j += 8)
        t[ty + j][tx] = f[((size_t)b*C_ + cb + ty + j)*N_ + nb + tx];
    __syncthreads();
#pragma unroll
    for (int j = 0; j < 32; j += 8)
        g_featT[((size_t)b*N_ + nb + ty + j)*C_ + cb + tx] = t[tx][ty + j];
}

/* ------------ FPS: one 512-thread block per batch, packed f32x2 ------------ */
#define FPS_SMEM (3*N_*4 + 64*4)
__global__ void __launch_bounds__(512, 1) k_fps(const float* __restrict__ coords) {
    extern __shared__ float sm[];
    float* sx = sm; float* sy = sm + N_; float* sz = sm + 2*N_;
    float*    wbv = sm + 3*N_;                 /* [2][16] */
    unsigned* wbn = (unsigned*)(wbv + 32);     /* [2][16] */
    int b = blockIdx.x, tid = threadIdx.x;
    int lane = tid & 31;
    int wid = tid >> 5;
    const float* cb = coords + (size_t)b*3*N_;

    ull pxp[8], pyp[8], pzp[8];
    float mind[16];
#pragma unroll
    for (int jj = 0; jj < 8; jj++) {
        int n0 = (2*jj)*512 + tid, n1 = n0 + 512;
        float x0 = cb[n0],        x1 = cb[n1];
        float y0 = cb[N_ + n0],   y1 = cb[N_ + n1];
        float z0 = cb[2*N_ + n0], z1 = cb[2*N_ + n1];
        sx[n0] = x0; sx[n1] = x1;
        sy[n0] = y0; sy[n1] = y1;
        sz[n0] = z0; sz[n1] = z1;
        pxp[jj] = pk2(x0, x1); pyp[jj] = pk2(y0, y1); pzp[jj] = pk2(z0, z1);
        mind[2*jj] = 1e10f; mind[2*jj+1] = 1e10f;
    }
    float lx = cb[0], ly = cb[N_], lz = cb[2*N_];
    if (tid == 0) {
        g_centers[(b*3+0)*S_] = lx;
        g_centers[(b*3+1)*S_] = ly;
        g_centers[(b*3+2)*S_] = lz;
    }
    __syncthreads();

    for (int step = 1; step < S_; ++step) {
        ull nlx = pk2(-lx, -lx), nly = pk2(-ly, -ly), nlz = pk2(-lz, -lz);
        float bd = -1.0f; unsigned bn = 0;
#pragma unroll
        for (int jj = 0; jj < 8; jj++) {
            ull dx = add2(pxp[jj], nlx);
            ull dy = add2(pyp[jj], nly);
            ull dz = add2(pzp[jj], nlz);
            ull s  = mul2(dx, dx);
            ull t  = mul2(dy, dy);
            s = add2(s, t);
            t = mul2(dz, dz);
            s = add2(s, t);
            float d0, d1; upk2(s, d0, d1);
            float m0 = fminf(mind[2*jj],   d0); mind[2*jj]   = m0;
            float m1 = fminf(mind[2*jj+1], d1); mind[2*jj+1] = m1;
            if (m0 > bd) { bd = m0; bn = (unsigned)((2*jj)*512 + tid); }
            if (m1 > bd) { bd = m1; bn = (unsigned)((2*jj+1)*512 + tid); }
        }
        /* warp reduce: max value, then min index among ties (first-occurrence) */
        float wv = bd;
#pragma unroll
        for (int off = 16; off; off >>= 1)
            wv = fmaxf(wv, __shfl_xor_sync(0xffffffffu, wv, off));
        unsigned cand = (bd == wv) ? bn : 0xffffffffu;
        unsigned wn = redmin(cand);
        int pb = (step & 1) * 16;
        if (lane == 0) { wbv[pb + wid] = wv; wbn[pb + wid] = wn; }
        __syncthreads();
        /* every warp reduces the 16 warp candidates (no 2nd barrier) */
        float v = wbv[pb + (lane & 15)];
        unsigned nn = wbn[pb + (lane & 15)];
        float vm = v;
#pragma unroll
        for (int off = 16; off; off >>= 1)
            vm = fmaxf(vm, __shfl_xor_sync(0xffffffffu, vm, off));
        unsigned c2 = (v == vm) ? nn : 0xffffffffu;
        unsigned win = redmin(c2);
        lx = sx[win]; ly = sy[win]; lz = sz[win];
        if (tid == 0) {
            g_centers[(b*3+0)*S_ + step] = lx;
            g_centers[(b*3+1)*S_ + step] = ly;
            g_centers[(b*3+2)*S_ + step] = lz;
        }
    }
}

/* ------------ ball query: warp per center (unchanged math) ------------ */
#define BALL_SMEM (3*N_*4)
__global__ void __launch_bounds__(256) k_ball(const float* __restrict__ coords) {
    extern __shared__ float sm[];
    float* sx = sm; float* sy = sm + N_; float* sz = sm + 2*N_;
    int blk = blockIdx.x;
    int b = blk >> 5, part = blk & 31;
    int tid = threadIdx.x;
    const float* cb = coords + (size_t)b*3*N_;
    for (int n = tid; n < N_; n += 256) {
        sx[n] = cb[n]; sy[n] = cb[N_ + n]; sz[n] = cb[2*N_ + n];
    }
    __syncthreads();
    int w = tid >> 5, lane = tid & 31;
    for (int cc = 0; cc < 8; cc++) {
        int s = part*64 + w*8 + cc;
        float cx = g_centers[(b*3+0)*S_ + s];
        float cy = g_centers[(b*3+1)*S_ + s];
        float cz = g_centers[(b*3+2)*S_ + s];
        float cn = __fadd_rn(__fadd_rn(__fmul_rn(cx,cx), __fmul_rn(cy,cy)), __fmul_rn(cz,cz));
        int found = 0, firstn = 0;
        int* op = &g_nidx[((size_t)b*S_ + s)*KNB];
        for (int base = 0; base < N_; base += 32) {
            int n = base + lane;
            float x = sx[n], y = sy[n], z = sz[n];
            float pn = __fadd_rn(__fadd_rn(__fmul_rn(x,x), __fmul_rn(y,y)), __fmul_rn(z,z));
            float cp = __fadd_rn(__fadd_rn(__fmul_rn(cx,x), __fmul_rn(cy,y)), __fmul_rn(cz,z));
            float d2 = __fsub_rn(__fadd_rn(cn, pn), __fmul_rn(2.0f, cp));
            bool hit = d2 < 0.0625f;
            unsigned bal = __ballot_sync(0xffffffffu, hit);
            if (bal) {
                if (found == 0) firstn = base + __ffs(bal) - 1;
                int slot = found + __popc(bal & ((1u << lane) - 1u));
                if (hit && slot < KNB) op[slot] = n;
                found += __popc(bal);
                if (found >= KNB) break;
            }
        }
        if (found < KNB) {
            int fill = (found > 0) ? firstn : 0;
            for (int sl = found + lane; sl < KNB; sl += 32) op[sl] = fill;
        }
    }
}

/* ------------ conv0: gather + (67->64) + bias -> bufA (packed fma) ------------ */
#define CONV0_SMEM (68*128*4 + 68*32*8 + 64*4)
__global__ void __launch_bounds__(128) k_conv0(const float* __restrict__ coords,
                                               const float* __restrict__ w0,
                                               const float* __restrict__ b0) {
    extern __shared__ float sm[];
    float* xs = sm;                       /* [68][128] */
    ull*   wp = (ull*)(sm + 68*128);      /* [68][32] packed out-pairs */
    float* bs = (float*)(wp + 68*32);
    int tid = threadIdx.x;
    int b = blockIdx.x >> 9;
    int p = (blockIdx.x & 511)*128 + tid;

    for (int k2 = tid; k2 < 68*32; k2 += 128) {
        int i = k2 >> 5, o2 = k2 & 31;
        float a = (i < 67) ? w0[(2*o2)*67 + i]   : 0.0f;
        float c = (i < 67) ? w0[(2*o2+1)*67 + i] : 0.0f;
        wp[k2] = pk2(a, c);
    }
    if (tid < 64) bs[tid] = b0[tid];

    int s = p >> 5;
    int n = g_nidx[((size_t)b*S_ + s)*KNB + (p & 31)];
    const float* cb = coords + (size_t)b*3*N_;
    xs[0*128 + tid] = __fsub_rn(cb[n],        g_centers[(b*3+0)*S_ + s]);
    xs[1*128 + tid] = __fsub_rn(cb[N_ + n],   g_centers[(b*3+1)*S_ + s]);
    xs[2*128 + tid] = __fsub_rn(cb[2*N_ + n], g_centers[(b*3+2)*S_ + s]);
    const float4* fp = (const float4*)(g_featT + ((size_t)b*N_ + n)*C_);
#pragma unroll
    for (int q = 0; q < 16; q++) {
        float4 v = fp[q]; int ib = 3 + 4*q;
        xs[(ib+0)*128 + tid] = v.x; xs[(ib+1)*128 + tid] = v.y;
        xs[(ib+2)*128 + tid] = v.z; xs[(ib+3)*128 + tid] = v.w;
    }
    xs[67*128 + tid] = 0.0f;
    __syncthreads();

    ull acc[32];
#pragma unroll
    for (int o2 = 0; o2 < 32; o2++) acc[o2] = pk2(bs[2*o2], bs[2*o2+1]);
#pragma unroll 2
    for (int i = 0; i < 68; i++) {
        float x = xs[i*128 + tid];
        ull xx = pk2(x, x);
        const ulonglong2* wr = (const ulonglong2*)(wp + i*32);
#pragma unroll
        for (int q = 0; q < 16; q++) {
            ulonglong2 w = wr[q];
            acc[2*q]   = fma2(w.x, xx, acc[2*q]);
            acc[2*q+1] = fma2(w.y, xx, acc[2*q+1]);
        }
    }
    float* yb = g_bufA + ((size_t)b*64)*PTS + p;
#pragma unroll
    for (int o2 = 0; o2 < 32; o2++) {
        float a0, a1; upk2(acc[o2], a0, a1);
        yb[(size_t)(2*o2)*PTS]   = a0;
        yb[(size_t)(2*o2+1)*PTS] = a1;
    }
}

/* ------------ per-(b,c) stats: deterministic two-stage ------------ */
template<int COUT, bool SRC_A>
__global__ void __launch_bounds__(256) k_stats(int off) {
    const float* y = SRC_A ? g_bufA : g_bufB;
    int bc = blockIdx.x;
    const float4* p4 = (const float4*)(y + (size_t)bc*PTS);
    float s = 0.0f, q = 0.0f;
    for (int i = threadIdx.x; i < PTS/4; i += 256) {
        float4 v = p4[i];
        s += v.x + v.y + v.z + v.w;
        q += v.x*v.x + v.y*v.y + v.z*v.z + v.w*v.w;
    }
    double ds = (double)s, dq = (double)q;
    int lane = threadIdx.x & 31, w = threadIdx.x >> 5;
#pragma unroll
    for (int o = 16; o; o >>= 1) {
        ds += __shfl_xor_sync(0xffffffffu, ds, o);
        dq += __shfl_xor_sync(0xffffffffu, dq, o);
    }
    __shared__ double sh[16];
    if (lane == 0) { sh[w] = ds; sh[8 + w] = dq; }
    __syncthreads();
    if (threadIdx.x == 0) {
        double S = 0.0, Q = 0.0;
#pragma unroll
        for (int i = 0; i < 8; i++) { S += sh[i]; Q += sh[8 + i]; }
        g_csum[off + bc] = S; g_csq[off + bc] = Q;
    }
}

/* ------------ convN: GN(prev) + SiLU + (64->COUT) + bias (packed fma) ------------ */
template<int COUT, bool IN_A>
__global__ void __launch_bounds__(128) k_convN(const float* __restrict__ w,
                                               const float* __restrict__ bb,
                                               const float* __restrict__ gamma,
                                               const float* __restrict__ beta,
                                               int off, double inv_cnt) {
    extern __shared__ float sm[];
    float* xs = sm;                        /* [64][128] */
    ull*   wp = (ull*)(sm + 64*128);       /* [64][COUT/2] */
    float* bs = (float*)(wp + 64*(COUT/2));
    float* al = bs + COUT;
    float* bt = al + 64;
    int tid = threadIdx.x;
    int b = blockIdx.x >> 9;
    int p = (blockIdx.x & 511)*128 + tid;
    const float* yin  = IN_A ? g_bufA : g_bufB;
    float*       yout = IN_A ? g_bufB : g_bufA;

    for (int k2 = tid; k2 < 64*(COUT/2); k2 += 128) {
        int i = k2 / (COUT/2), o2 = k2 - i*(COUT/2);
        wp[k2] = pk2(w[(2*o2)*64 + i], w[(2*o2+1)*64 + i]);
    }
    if (tid < COUT) bs[tid] = bb[tid];
    if (tid < 64) {
        int g = tid >> 3;
        double ms = 0.0, qs = 0.0;
#pragma unroll
        for (int cc = 0; cc < 8; cc++) {
            ms += g_csum[off + b*64 + g*8 + cc];
            qs += g_csq [off + b*64 + g*8 + cc];
        }
        double mu  = ms * inv_cnt;
        double var = qs * inv_cnt - mu*mu;
        float rstd = (float)rsqrt(var + 1e-5);
        float a = gamma[tid] * rstd;
        al[tid] = a;
        bt[tid] = beta[tid] - (float)mu * a;
    }
    __syncthreads();

#pragma unroll 1
    for (int ci = 0; ci < 64; ci++) {
        float v  = yin[((size_t)b*64 + ci)*PTS + p];
        float xn = fmaf(v, al[ci], bt[ci]);
        float sg = __fdividef(1.0f, 1.0f + __expf(-xn));
        xs[ci*128 + tid] = xn * sg;
    }
    __syncthreads();

    ull acc[COUT/2];
#pragma unroll
    for (int o2 = 0; o2 < COUT/2; o2++) acc[o2] = pk2(bs[2*o2], bs[2*o2+1]);
#pragma unroll 2
    for (int i = 0; i < 64; i++) {
        float x = xs[i*128 + tid];
        ull xx = pk2(x, x);
        const ulonglong2* wr = (const ulonglong2*)(wp + i*(COUT/2));
#pragma unroll
        for (int q = 0; q < COUT/4; q++) {
            ulonglong2 wv = wr[q];
            acc[2*q]   = fma2(wv.x, xx, acc[2*q]);
            acc[2*q+1] = fma2(wv.y, xx, acc[2*q+1]);
        }
    }
    float* yb = yout + ((size_t)b*COUT)*PTS + p;
#pragma unroll
    for (int o2 = 0; o2 < COUT/2; o2++) {
        float a0, a1; upk2(acc[o2], a0, a1);
        yb[(size_t)(2*o2)*PTS]   = a0;
        yb[(size_t)(2*o2+1)*PTS] = a1;
    }
}

/* ------------ final: GN + SiLU + max over K ------------ */
__global__ void __launch_bounds__(256) k_final(const float* __restrict__ gamma,
                                               const float* __restrict__ beta,
                                               float* __restrict__ out,
                                               int off, double inv_cnt) {
    int blk = blockIdx.x;
    int bc = blk >> 5;
    int chunk = blk & 31;
    int b = bc >> 7, c = bc & 127;
    __shared__ float s_a, s_b;
    if (threadIdx.x == 0) {
        int g = c >> 4;
        double ms = 0.0, qs = 0.0;
#pragma unroll
        for (int cc = 0; cc < 16; cc++) {
            ms += g_csum[off + b*128 + g*16 + cc];
            qs += g_csq [off + b*128 + g*16 + cc];
        }
        double mu  = ms * inv_cnt;
        double var = qs * inv_cnt - mu*mu;
        float rstd = (float)rsqrt(var + 1e-5);
        float a = gamma[c] * rstd;
        s_a = a;
        s_b = beta[c] - (float)mu * a;
    }
    __syncthreads();
    float a = s_a, bt = s_b;
    int w = threadIdx.x >> 5, lane = threadIdx.x & 31;
    const float* base = g_bufA + (size_t)bc*PTS;
#pragma unroll 1
    for (int j = 0; j < 8; j++) {
        int s = chunk*64 + w*8 + j;
        float v  = base[s*32 + lane];
        float xn = fmaf(v, a, bt);
        float sg = __fdividef(1.0f, 1.0f + __expf(-xn));
        float val = xn * sg;
#pragma unroll
        for (int o = 16; o; o >>= 1)
            val = fmaxf(val, __shfl_xor_sync(0xffffffffu, val, o));
        if (lane == 0) out[(size_t)bc*S_ + s] = val;
    }
}

extern "C" void kernel_launch(void* const* d_in, const int* in_sizes, int n_in,
                              void* d_out, int out_size) {
    const float* coords   = (const float*)d_in[0];
    const float* features = (const float*)d_in[1];
    const float* w0 = (const float*)d_in[2];
    const float* b0 = (const float*)d_in[3];
    const float* g0 = (const float*)d_in[4];
    const float* be0= (const float*)d_in[5];
    const float* w1 = (const float*)d_in[6];
    const float* b1 = (const float*)d_in[7];
    const float* g1 = (const float*)d_in[8];
    const float* be1= (const float*)d_in[9];
    const float* w2 = (const float*)d_in[10];
    const float* b2 = (const float*)d_in[11];
    const float* g2 = (const float*)d_in[12];
    const float* be2= (const float*)d_in[13];
    float* out = (float*)d_out;

    int smN64  = 64*128*4 + 64*32*8 + (64+64+64)*4;
    int smN128 = 64*128*4 + 64*64*8 + (128+64+64)*4;
    cudaFuncSetAttribute(k_fps,   cudaFuncAttributeMaxDynamicSharedMemorySize, FPS_SMEM);
    cudaFuncSetAttribute(k_ball,  cudaFuncAttributeMaxDynamicSharedMemorySize, BALL_SMEM);
    cudaFuncSetAttribute(k_conv0, cudaFuncAttributeMaxDynamicSharedMemorySize, CONV0_SMEM);
    cudaFuncSetAttribute(k_convN<64,true>,   cudaFuncAttributeMaxDynamicSharedMemorySize, smN64);
    cudaFuncSetAttribute(k_convN<128,false>, cudaFuncAttributeMaxDynamicSharedMemorySize, smN128);

    dim3 tg(N_/32, C_/32, B_);
    k_transpose<<<tg, dim3(32,8)>>>(features);
    k_fps<<<B_, 512, FPS_SMEM>>>(coords);
    k_ball<<<B_*32, 256, BALL_SMEM>>>(coords);
    k_conv0<<<B_*512, 128, CONV0_SMEM>>>(coords, w0, b0);
    k_stats<64,true><<<B_*64, 256>>>(0);
    k_convN<64,true><<<B_*512, 128, smN64>>>(w1, b1, g0, be0, 0, 1.0/(8.0*PTS));
    k_stats<64,false><<<B_*64, 256>>>(512);
    k_convN<128,false><<<B_*512, 128, smN128>>>(w2, b2, g1, be1, 512, 1.0/(8.0*PTS));
    k_stats<128,true><<<B_*128, 256>>>(1024);
    k_final<<<B_*128*32, 256>>>(g2, be2, out, 1024, 1.0/(16.0*PTS));
}

// round 4
// speedup vs baseline: 1.3748x; 1.1656x over previous
#include <cuda_runtime.h>
#include <math.h>
#include <stdint.h>

#define B_  8
#define N_  8192
#define C_  64
#define S_  2048
#define KNB 32
#define PTS (S_*KNB)
typedef unsigned long long ull;

__device__ float  g_featT[(size_t)B_*N_*C_];
__device__ float  g_centers[B_*3*S_];
__device__ int    g_nidx[B_*S_*KNB];
__device__ float  g_bufA[(size_t)B_*128*PTS];
__device__ float  g_bufB[(size_t)B_*128*PTS];
__device__ double g_csum[2048];
__device__ double g_csq [2048];

__device__ __forceinline__ ull pk2(float lo, float hi) {
    ull r; asm("mov.b64 %0,{%1,%2};" : "=l"(r) : "f"(lo), "f"(hi)); return r;
}
__device__ __forceinline__ void upk2(ull v, float& lo, float& hi) {
    asm("mov.b64 {%0,%1},%2;" : "=f"(lo), "=f"(hi) : "l"(v));
}
__device__ __forceinline__ ull add2(ull a, ull b) {
    ull r; asm("add.rn.f32x2 %0,%1,%2;" : "=l"(r) : "l"(a), "l"(b)); return r;
}
__device__ __forceinline__ ull mul2(ull a, ull b) {
    ull r; asm("mul.rn.f32x2 %0,%1,%2;" : "=l"(r) : "l"(a), "l"(b)); return r;
}
__device__ __forceinline__ ull fma2(ull a, ull b, ull c) {
    ull r; asm("fma.rn.f32x2 %0,%1,%2,%3;" : "=l"(r) : "l"(a), "l"(b), "l"(c)); return r;
}

/* ------------ transpose features [b][c][n] -> [b][n][c] ------------ */
__global__ void k_transpose(const float* __restrict__ f) {
    __shared__ float t[32][33];
    int b = blockIdx.z;
    int nb = blockIdx.x * 32, cb = blockIdx.y * 32;
    int tx = threadIdx.x, ty = threadIdx.y;
#pragma unroll
    for (int j = 0; j < 32; j += 8)
        t[ty + j][tx] = f[((size_t)b*C_ + cb + ty + j)*N_ + nb + tx];
    __syncthreads();
#pragma unroll
    for (int j = 0; j < 32; j += 8)
        g_featT[((size_t)b*N_ + nb + ty + j)*C_ + cb + tx] = t[tx][ty + j];
}

/* ------------ FPS: one 512-thread block per batch ------------ */
#define FPS_SMEM (3*N_*4 + 64*4)
__global__ void __launch_bounds__(512, 1) k_fps(const float* __restrict__ coords) {
    extern __shared__ float sm[];
    float* sx = sm; float* sy = sm + N_; float* sz = sm + 2*N_;
    unsigned* wbv = (unsigned*)(sm + 3*N_);     /* [2][16] value bits */
    unsigned* wbn = wbv + 32;                   /* [2][16] index      */
    int b = blockIdx.x, tid = threadIdx.x;
    int lane = tid & 31;
    int wid = tid >> 5;
    const float* cb = coords + (size_t)b*3*N_;

    ull pxp[8], pyp[8], pzp[8];
    float mind[16];
#pragma unroll
    for (int jj = 0; jj < 8; jj++) {
        int n0 = (2*jj)*512 + tid, n1 = n0 + 512;
        float x0 = cb[n0],        x1 = cb[n1];
        float y0 = cb[N_ + n0],   y1 = cb[N_ + n1];
        float z0 = cb[2*N_ + n0], z1 = cb[2*N_ + n1];
        sx[n0] = x0; sx[n1] = x1;
        sy[n0] = y0; sy[n1] = y1;
        sz[n0] = z0; sz[n1] = z1;
        pxp[jj] = pk2(x0, x1); pyp[jj] = pk2(y0, y1); pzp[jj] = pk2(z0, z1);
        mind[2*jj] = 1e10f; mind[2*jj+1] = 1e10f;
    }
    float lx = cb[0], ly = cb[N_], lz = cb[2*N_];
    if (tid == 0) {
        g_centers[(b*3+0)*S_] = lx;
        g_centers[(b*3+1)*S_] = ly;
        g_centers[(b*3+2)*S_] = lz;
    }
    __syncthreads();

    for (int step = 1; step < S_; ++step) {
        ull nlx = pk2(-lx, -lx), nly = pk2(-ly, -ly), nlz = pk2(-lz, -lz);
        float bd = -1.0f;
#pragma unroll
        for (int jj = 0; jj < 8; jj++) {
            ull dx = add2(pxp[jj], nlx);
            ull dy = add2(pyp[jj], nly);
            ull dz = add2(pzp[jj], nlz);
            ull s  = mul2(dx, dx);
            ull t  = mul2(dy, dy);
            s = add2(s, t);
            t = mul2(dz, dz);
            s = add2(s, t);
            float d0, d1; upk2(s, d0, d1);
            float m0 = fminf(mind[2*jj],   d0); mind[2*jj]   = m0;
            float m1 = fminf(mind[2*jj+1], d1); mind[2*jj+1] = m1;
            bd = fmaxf(bd, m0);
            bd = fmaxf(bd, m1);
        }
        /* positive floats: fp max == u32-bit max */
        unsigned bdb = __float_as_uint(bd);
        unsigned wv  = __reduce_max_sync(0xffffffffu, bdb);
        unsigned cand = 0xffffffffu;
        if (bdb == wv) {
#pragma unroll
            for (int j = 15; j >= 0; j--)
                if (__float_as_uint(mind[j]) == wv)
                    cand = (unsigned)(j*512 + tid);
        }
        unsigned wn = __reduce_min_sync(0xffffffffu, cand);
        int pb = (step & 1) * 16;
        if (lane == 0) { wbv[pb + wid] = wv; wbn[pb + wid] = wn; }
        __syncthreads();
        /* every warp reduces the 16 warp candidates (no 2nd barrier) */
        unsigned v  = wbv[pb + (lane & 15)];
        unsigned nn = wbn[pb + (lane & 15)];
        unsigned vm = __reduce_max_sync(0xffffffffu, v);
        unsigned c2 = (v == vm) ? nn : 0xffffffffu;
        unsigned win = __reduce_min_sync(0xffffffffu, c2);
        lx = sx[win]; ly = sy[win]; lz = sz[win];
        if (tid == 0) {
            g_centers[(b*3+0)*S_ + step] = lx;
            g_centers[(b*3+1)*S_ + step] = ly;
            g_centers[(b*3+2)*S_ + step] = lz;
        }
    }
}

/* ------------ ball query: warp per center ------------ */
#define BALL_SMEM (3*N_*4)
__global__ void __launch_bounds__(256) k_ball(const float* __restrict__ coords) {
    extern __shared__ float sm[];
    float* sx = sm; float* sy = sm + N_; float* sz = sm + 2*N_;
    int blk = blockIdx.x;
    int b = blk >> 5, part = blk & 31;
    int tid = threadIdx.x;
    const float* cb = coords + (size_t)b*3*N_;
    for (int n = tid; n < N_; n += 256) {
        sx[n] = cb[n]; sy[n] = cb[N_ + n]; sz[n] = cb[2*N_ + n];
    }
    __syncthreads();
    int w = tid >> 5, lane = tid & 31;
    for (int cc = 0; cc < 8; cc++) {
        int s = part*64 + w*8 + cc;
        float cx = g_centers[(b*3+0)*S_ + s];
        float cy = g_centers[(b*3+1)*S_ + s];
        float cz = g_centers[(b*3+2)*S_ + s];
        float cn = __fadd_rn(__fadd_rn(__fmul_rn(cx,cx), __fmul_rn(cy,cy)), __fmul_rn(cz,cz));
        int found = 0, firstn = 0;
        int* op = &g_nidx[((size_t)b*S_ + s)*KNB];
        for (int base = 0; base < N_; base += 32) {
            int n = base + lane;
            float x = sx[n], y = sy[n], z = sz[n];
            float pn = __fadd_rn(__fadd_rn(__fmul_rn(x,x), __fmul_rn(y,y)), __fmul_rn(z,z));
            float cp = __fadd_rn(__fadd_rn(__fmul_rn(cx,x), __fmul_rn(cy,y)), __fmul_rn(cz,z));
            float d2 = __fsub_rn(__fadd_rn(cn, pn), __fmul_rn(2.0f, cp));
            bool hit = d2 < 0.0625f;
            unsigned bal = __ballot_sync(0xffffffffu, hit);
            if (bal) {
                if (found == 0) firstn = base + __ffs(bal) - 1;
                int slot = found + __popc(bal & ((1u << lane) - 1u));
                if (hit && slot < KNB) op[slot] = n;
                found += __popc(bal);
                if (found >= KNB) break;
            }
        }
        if (found < KNB) {
            int fill = (found > 0) ? firstn : 0;
            for (int sl = found + lane; sl < KNB; sl += 32) op[sl] = fill;
        }
    }
}

/* ------------ conv0: gather + (67->64) + bias -> bufA (packed fma) ------------ */
#define CONV0_SMEM (68*128*4 + 68*32*8 + 64*4)
__global__ void __launch_bounds__(128) k_conv0(const float* __restrict__ coords,
                                               const float* __restrict__ w0,
                                               const float* __restrict__ b0) {
    extern __shared__ float sm[];
    float* xs = sm;                       /* [68][128] */
    ull*   wp = (ull*)(sm + 68*128);      /* [68][32] packed out-pairs */
    float* bs = (float*)(wp + 68*32);
    int tid = threadIdx.x;
    int b = blockIdx.x >> 9;
    int p = (blockIdx.x & 511)*128 + tid;

    for (int k2 = tid; k2 < 68*32; k2 += 128) {
        int i = k2 >> 5, o2 = k2 & 31;
        float a = (i < 67) ? w0[(2*o2)*67 + i]   : 0.0f;
        float c = (i < 67) ? w0[(2*o2+1)*67 + i] : 0.0f;
        wp[k2] = pk2(a, c);
    }
    if (tid < 64) bs[tid] = b0[tid];

    int s = p >> 5;
    int n = g_nidx[((size_t)b*S_ + s)*KNB + (p & 31)];
    const float* cb = coords + (size_t)b*3*N_;
    xs[0*128 + tid] = __fsub_rn(cb[n],        g_centers[(b*3+0)*S_ + s]);
    xs[1*128 + tid] = __fsub_rn(cb[N_ + n],   g_centers[(b*3+1)*S_ + s]);
    xs[2*128 + tid] = __fsub_rn(cb[2*N_ + n], g_centers[(b*3+2)*S_ + s]);
    const float4* fp = (const float4*)(g_featT + ((size_t)b*N_ + n)*C_);
#pragma unroll
    for (int q = 0; q < 16; q++) {
        float4 v = fp[q]; int ib = 3 + 4*q;
        xs[(ib+0)*128 + tid] = v.x; xs[(ib+1)*128 + tid] = v.y;
        xs[(ib+2)*128 + tid] = v.z; xs[(ib+3)*128 + tid] = v.w;
    }
    xs[67*128 + tid] = 0.0f;
    __syncthreads();

    ull acc[32];
#pragma unroll
    for (int o2 = 0; o2 < 32; o2++) acc[o2] = pk2(bs[2*o2], bs[2*o2+1]);
#pragma unroll 2
    for (int i = 0; i < 68; i++) {
        float x = xs[i*128 + tid];
        ull xx = pk2(x, x);
        const ulonglong2* wr = (const ulonglong2*)(wp + i*32);
#pragma unroll
        for (int q = 0; q < 16; q++) {
            ulonglong2 w = wr[q];
            acc[2*q]   = fma2(w.x, xx, acc[2*q]);
            acc[2*q+1] = fma2(w.y, xx, acc[2*q+1]);
        }
    }
    float* yb = g_bufA + ((size_t)b*64)*PTS + p;
#pragma unroll
    for (int o2 = 0; o2 < 32; o2++) {
        float a0, a1; upk2(acc[o2], a0, a1);
        yb[(size_t)(2*o2)*PTS]   = a0;
        yb[(size_t)(2*o2+1)*PTS] = a1;
    }
}

/* ------------ per-(b,c) stats: deterministic two-stage ------------ */
template<int COUT, bool SRC_A>
__global__ void __launch_bounds__(256) k_stats(int off) {
    const float* y = SRC_A ? g_bufA : g_bufB;
    int bc = blockIdx.x;
    const float4* p4 = (const float4*)(y + (size_t)bc*PTS);
    float s = 0.0f, q = 0.0f;
    for (int i = threadIdx.x; i < PTS/4; i += 256) {
        float4 v = p4[i];
        s += v.x + v.y + v.z + v.w;
        q += v.x*v.x + v.y*v.y + v.z*v.z + v.w*v.w;
    }
    double ds = (double)s, dq = (double)q;
    int lane = threadIdx.x & 31, w = threadIdx.x >> 5;
#pragma unroll
    for (int o = 16; o; o >>= 1) {
        ds += __shfl_xor_sync(0xffffffffu, ds, o);
        dq += __shfl_xor_sync(0xffffffffu, dq, o);
    }
    __shared__ double sh[16];
    if (lane == 0) { sh[w] = ds; sh[8 + w] = dq; }
    __syncthreads();
    if (threadIdx.x == 0) {
        double S = 0.0, Q = 0.0;
#pragma unroll
        for (int i = 0; i < 8; i++) { S += sh[i]; Q += sh[8 + i]; }
        g_csum[off + bc] = S; g_csq[off + bc] = Q;
    }
}

/* ------------ convN64: GN(prev) + SiLU + (64->64) + bias ------------ */
__global__ void __launch_bounds__(128) k_convN64(const float* __restrict__ w,
                                                 const float* __restrict__ bb,
                                                 const float* __restrict__ gamma,
                                                 const float* __restrict__ beta,
                                                 int off, double inv_cnt) {
    extern __shared__ float sm[];
    float* xs = sm;                        /* [64][128] */
    ull*   wp = (ull*)(sm + 64*128);       /* [64][32] */
    float* bs = (float*)(wp + 64*32);
    float* al = bs + 64;
    float* bt = al + 64;
    int tid = threadIdx.x;
    int b = blockIdx.x >> 9;
    int p = (blockIdx.x & 511)*128 + tid;

    for (int k2 = tid; k2 < 64*32; k2 += 128) {
        int i = k2 >> 5, o2 = k2 & 31;
        wp[k2] = pk2(w[(2*o2)*64 + i], w[(2*o2+1)*64 + i]);
    }
    if (tid < 64) bs[tid] = bb[tid];
    if (tid < 64) {
        int g = tid >> 3;
        double ms = 0.0, qs = 0.0;
#pragma unroll
        for (int cc = 0; cc < 8; cc++) {
            ms += g_csum[off + b*64 + g*8 + cc];
            qs += g_csq [off + b*64 + g*8 + cc];
        }
        double mu  = ms * inv_cnt;
        double var = qs * inv_cnt - mu*mu;
        float rstd = (float)rsqrt(var + 1e-5);
        float a = gamma[tid] * rstd;
        al[tid] = a;
        bt[tid] = beta[tid] - (float)mu * a;
    }
    __syncthreads();

#pragma unroll 1
    for (int ci = 0; ci < 64; ci++) {
        float v  = g_bufA[((size_t)b*64 + ci)*PTS + p];
        float xn = fmaf(v, al[ci], bt[ci]);
        float sg = __fdividef(1.0f, 1.0f + __expf(-xn));
        xs[ci*128 + tid] = xn * sg;
    }
    __syncthreads();

    ull acc[32];
#pragma unroll
    for (int o2 = 0; o2 < 32; o2++) acc[o2] = pk2(bs[2*o2], bs[2*o2+1]);
#pragma unroll 2
    for (int i = 0; i < 64; i++) {
        float x = xs[i*128 + tid];
        ull xx = pk2(x, x);
        const ulonglong2* wr = (const ulonglong2*)(wp + i*32);
#pragma unroll
        for (int q = 0; q < 16; q++) {
            ulonglong2 wv = wr[q];
            acc[2*q]   = fma2(wv.x, xx, acc[2*q]);
            acc[2*q+1] = fma2(wv.y, xx, acc[2*q+1]);
        }
    }
    float* yb = g_bufB + ((size_t)b*64)*PTS + p;
#pragma unroll
    for (int o2 = 0; o2 < 32; o2++) {
        float a0, a1; upk2(acc[o2], a0, a1);
        yb[(size_t)(2*o2)*PTS]   = a0;
        yb[(size_t)(2*o2+1)*PTS] = a1;
    }
}

/* ------------ conv128: GN + SiLU + (64->128), 256 thr, 4 out-groups x 2 pts ------------ */
#define CONV128_SMEM (64*128*4 + 64*64*8 + (128+64+64)*4)
__global__ void __launch_bounds__(256) k_conv128(const float* __restrict__ w,
                                                 const float* __restrict__ bb,
                                                 const float* __restrict__ gamma,
                                                 const float* __restrict__ beta,
                                                 int off, double inv_cnt) {
    extern __shared__ float sm[];
    float* xs = sm;                        /* [64][128] */
    ull*   wp = (ull*)(sm + 64*128);       /* [64][64] out-pairs */
    float* bs = (float*)(wp + 64*64);      /* [128] */
    float* al = bs + 128;
    float* bt = al + 64;
    int tid = threadIdx.x;
    int b = blockIdx.x >> 9;
    int pbase = (blockIdx.x & 511)*128;

    for (int k2 = tid; k2 < 64*64; k2 += 256) {
        int i = k2 >> 6, o2 = k2 & 63;
        wp[k2] = pk2(w[(2*o2)*64 + i], w[(2*o2+1)*64 + i]);
    }
    if (tid < 128) bs[tid] = bb[tid];
    if (tid < 64) {
        int g = tid >> 3;
        double ms = 0.0, qs = 0.0;
#pragma unroll
        for (int cc = 0; cc < 8; cc++) {
            ms += g_csum[off + b*64 + g*8 + cc];
            qs += g_csq [off + b*64 + g*8 + cc];
        }
        double mu  = ms * inv_cnt;
        double var = qs * inv_cnt - mu*mu;
        float rstd = (float)rsqrt(var + 1e-5);
        float a = gamma[tid] * rstd;
        al[tid] = a;
        bt[tid] = beta[tid] - (float)mu * a;
    }
    __syncthreads();

    /* GN+SiLU staging: half h handles ci in [h*32, h*32+32) for point pt */
    {
        int h = tid >> 7, pt = tid & 127;
        int p = pbase + pt;
#pragma unroll 1
        for (int cc = 0; cc < 32; cc++) {
            int ci = h*32 + cc;
            float v  = g_bufB[((size_t)b*64 + ci)*PTS + p];
            float xn = fmaf(v, al[ci], bt[ci]);
            float sg = __fdividef(1.0f, 1.0f + __expf(-xn));
            xs[ci*128 + pt] = xn * sg;
        }
    }
    __syncthreads();

    int og  = tid >> 6;            /* 0..3: outputs og*32..og*32+31 */
    int pt0 = (tid & 63) * 2;      /* point pair */
    ull acc0[16], acc1[16];
#pragma unroll
    for (int q = 0; q < 16; q++) {
        ull bv = pk2(bs[og*32 + 2*q], bs[og*32 + 2*q + 1]);
        acc0[q] = bv; acc1[q] = bv;
    }
#pragma unroll 2
    for (int i = 0; i < 64; i++) {
        ull xv = *(const ull*)(xs + i*128 + pt0);
        float x0, x1; upk2(xv, x0, x1);
        ull xx0 = pk2(x0, x0), xx1 = pk2(x1, x1);
        const ulonglong2* wr = (const ulonglong2*)(wp + i*64 + og*16);
#pragma unroll
        for (int q = 0; q < 8; q++) {
            ulonglong2 wq = wr[q];
            acc0[2*q]   = fma2(wq.x, xx0, acc0[2*q]);
            acc1[2*q]   = fma2(wq.x, xx1, acc1[2*q]);
            acc0[2*q+1] = fma2(wq.y, xx0, acc0[2*q+1]);
            acc1[2*q+1] = fma2(wq.y, xx1, acc1[2*q+1]);
        }
    }
    float* yb = g_bufA + ((size_t)b*128)*PTS + pbase + pt0;
#pragma unroll
    for (int q = 0; q < 16; q++) {
        int o = og*32 + 2*q;
        float a00, a01, a10, a11;
        upk2(acc0[q], a00, a01);
        upk2(acc1[q], a10, a11);
        *(float2*)(yb + (size_t)o*PTS)       = make_float2(a00, a10);
        *(float2*)(yb + (size_t)(o+1)*PTS)   = make_float2(a01, a11);
    }
}

/* ------------ final: GN + SiLU + max over K ------------ */
__global__ void __launch_bounds__(256) k_final(const float* __restrict__ gamma,
                                               const float* __restrict__ beta,
                                               float* __restrict__ out,
                                               int off, double inv_cnt) {
    int blk = blockIdx.x;
    int bc = blk >> 5;
    int chunk = blk & 31;
    int b = bc >> 7, c = bc & 127;
    __shared__ float s_a, s_b;
    if (threadIdx.x == 0) {
        int g = c >> 4;
        double ms = 0.0, qs = 0.0;
#pragma unroll
        for (int cc = 0; cc < 16; cc++) {
            ms += g_csum[off + b*128 + g*16 + cc];
            qs += g_csq [off + b*128 + g*16 + cc];
        }
        double mu  = ms * inv_cnt;
        double var = qs * inv_cnt - mu*mu;
        float rstd = (float)rsqrt(var + 1e-5);
        float a = gamma[c] * rstd;
        s_a = a;
        s_b = beta[c] - (float)mu * a;
    }
    __syncthreads();
    float a = s_a, bt = s_b;
    int w = threadIdx.x >> 5, lane = threadIdx.x & 31;
    const float* base = g_bufA + (size_t)bc*PTS;
#pragma unroll 1
    for (int j = 0; j < 8; j++) {
        int s = chunk*64 + w*8 + j;
        float v  = base[s*32 + lane];
        float xn = fmaf(v, a, bt);
        float sg = __fdividef(1.0f, 1.0f + __expf(-xn));
        float val = xn * sg;
#pragma unroll
        for (int o = 16; o; o >>= 1)
            val = fmaxf(val, __shfl_xor_sync(0xffffffffu, val, o));
        if (lane == 0) out[(size_t)bc*S_ + s] = val;
    }
}

extern "C" void kernel_launch(void* const* d_in, const int* in_sizes, int n_in,
                              void* d_out, int out_size) {
    const float* coords   = (const float*)d_in[0];
    const float* features = (const float*)d_in[1];
    const float* w0 = (const float*)d_in[2];
    const float* b0 = (const float*)d_in[3];
    const float* g0 = (const float*)d_in[4];
    const float* be0= (const float*)d_in[5];
    const float* w1 = (const float*)d_in[6];
    const float* b1 = (const float*)d_in[7];
    const float* g1 = (const float*)d_in[8];
    const float* be1= (const float*)d_in[9];
    const float* w2 = (const float*)d_in[10];
    const float* b2 = (const float*)d_in[11];
    const float* g2 = (const float*)d_in[12];
    const float* be2= (const float*)d_in[13];
    float* out = (float*)d_out;

    int smN64 = 64*128*4 + 64*32*8 + (64+64+64)*4;
    cudaFuncSetAttribute(k_fps,     cudaFuncAttributeMaxDynamicSharedMemorySize, FPS_SMEM);
    cudaFuncSetAttribute(k_ball,    cudaFuncAttributeMaxDynamicSharedMemorySize, BALL_SMEM);
    cudaFuncSetAttribute(k_conv0,   cudaFuncAttributeMaxDynamicSharedMemorySize, CONV0_SMEM);
    cudaFuncSetAttribute(k_convN64, cudaFuncAttributeMaxDynamicSharedMemorySize, smN64);
    cudaFuncSetAttribute(k_conv128, cudaFuncAttributeMaxDynamicSharedMemorySize, CONV128_SMEM);

    dim3 tg(N_/32, C_/32, B_);
    k_transpose<<<tg, dim3(32,8)>>>(features);
    k_fps<<<B_, 512, FPS_SMEM>>>(coords);
    k_ball<<<B_*32, 256, BALL_SMEM>>>(coords);
    k_conv0<<<B_*512, 128, CONV0_SMEM>>>(coords, w0, b0);
    k_stats<64,true><<<B_*64, 256>>>(0);
    k_convN64<<<B_*512, 128, smN64>>>(w1, b1, g0, be0, 0, 1.0/(8.0*PTS));
    k_stats<64,false><<<B_*64, 256>>>(512);
    k_conv128<<<B_*512, 256, CONV128_SMEM>>>(w2, b2, g1, be1, 512, 1.0/(8.0*PTS));
    k_stats<128,true><<<B_*128, 256>>>(1024);
    k_final<<<B_*128*32, 256>>>(g2, be2, out, 1024, 1.0/(16.0*PTS));
}

// round 6
// speedup vs baseline: 1.4233x; 1.0352x over previous
#include <cuda_runtime.h>
#include <math.h>
#include <stdint.h>

#define B_  8
#define N_  8192
#define C_  64
#define S_  2048
#define KNB 32
#define PTS (S_*KNB)
typedef unsigned long long ull;

__device__ float  g_featT[(size_t)B_*N_*C_];
__device__ float  g_centers[B_*3*S_];
__device__ int    g_nidx[B_*S_*KNB];
__device__ float  g_bufA[(size_t)B_*128*PTS];
__device__ float  g_bufB[(size_t)B_*128*PTS];
__device__ double g_csum[2048];
__device__ double g_csq [2048];

__device__ __forceinline__ ull pk2(float lo, float hi) {
    ull r; asm("mov.b64 %0,{%1,%2};" : "=l"(r) : "f"(lo), "f"(hi)); return r;
}
__device__ __forceinline__ void upk2(ull v, float& lo, float& hi) {
    asm("mov.b64 {%0,%1},%2;" : "=f"(lo), "=f"(hi) : "l"(v));
}
__device__ __forceinline__ ull add2(ull a, ull b) {
    ull r; asm("add.rn.f32x2 %0,%1,%2;" : "=l"(r) : "l"(a), "l"(b)); return r;
}
__device__ __forceinline__ ull mul2(ull a, ull b) {
    ull r; asm("mul.rn.f32x2 %0,%1,%2;" : "=l"(r) : "l"(a), "l"(b)); return r;
}
__device__ __forceinline__ ull fma2(ull a, ull b, ull c) {
    ull r; asm("fma.rn.f32x2 %0,%1,%2,%3;" : "=l"(r) : "l"(a), "l"(b), "l"(c)); return r;
}

/* ------------ transpose features [b][c][n] -> [b][n][c] ------------ */
__global__ void k_transpose(const float* __restrict__ f) {
    __shared__ float t[32][33];
    int b = blockIdx.z;
    int nb = blockIdx.x * 32, cb = blockIdx.y * 32;
    int tx = threadIdx.x, ty = threadIdx.y;
#pragma unroll
    for (int j = 0; j < 32; j += 8)
        t[ty + j][tx] = f[((size_t)b*C_ + cb + ty + j)*N_ + nb + tx];
    __syncthreads();
#pragma unroll
    for (int j = 0; j < 32; j += 8)
        g_featT[((size_t)b*N_ + nb + ty + j)*C_ + cb + tx] = t[tx][ty + j];
}

/* ------------ FPS: one 512-thread block per batch ------------ */
#define FPS_SMEM (3*N_*4 + 64*4)
__global__ void __launch_bounds__(512, 1) k_fps(const float* __restrict__ coords) {
    extern __shared__ float sm[];
    float* sx = sm; float* sy = sm + N_; float* sz = sm + 2*N_;
    unsigned* wbv = (unsigned*)(sm + 3*N_);     /* [2][16] value bits */
    unsigned* wbn = wbv + 32;                   /* [2][16] index      */
    int b = blockIdx.x, tid = threadIdx.x;
    int lane = tid & 31;
    int wid = tid >> 5;
    const float* cb = coords + (size_t)b*3*N_;

    ull pxp[8], pyp[8], pzp[8];
    float mind[16];
#pragma unroll
    for (int jj = 0; jj < 8; jj++) {
        int n0 = (2*jj)*512 + tid, n1 = n0 + 512;
        float x0 = cb[n0],        x1 = cb[n1];
        float y0 = cb[N_ + n0],   y1 = cb[N_ + n1];
        float z0 = cb[2*N_ + n0], z1 = cb[2*N_ + n1];
        sx[n0] = x0; sx[n1] = x1;
        sy[n0] = y0; sy[n1] = y1;
        sz[n0] = z0; sz[n1] = z1;
        pxp[jj] = pk2(x0, x1); pyp[jj] = pk2(y0, y1); pzp[jj] = pk2(z0, z1);
        mind[2*jj] = 1e10f; mind[2*jj+1] = 1e10f;
    }
    float lx = cb[0], ly = cb[N_], lz = cb[2*N_];
    if (tid == 0) {
        g_centers[(b*3+0)*S_] = lx;
        g_centers[(b*3+1)*S_] = ly;
        g_centers[(b*3+2)*S_] = lz;
    }
    __syncthreads();

    for (int step = 1; step < S_; ++step) {
        ull nlx = pk2(-lx, -lx), nly = pk2(-ly, -ly), nlz = pk2(-lz, -lz);
        float bd = -1.0f;
#pragma unroll
        for (int jj = 0; jj < 8; jj++) {
            ull dx = add2(pxp[jj], nlx);
            ull dy = add2(pyp[jj], nly);
            ull dz = add2(pzp[jj], nlz);
            ull s  = mul2(dx, dx);
            ull t  = mul2(dy, dy);
            s = add2(s, t);
            t = mul2(dz, dz);
            s = add2(s, t);
            float d0, d1; upk2(s, d0, d1);
            float m0 = fminf(mind[2*jj],   d0); mind[2*jj]   = m0;
            float m1 = fminf(mind[2*jj+1], d1); mind[2*jj+1] = m1;
            bd = fmaxf(bd, m0);
            bd = fmaxf(bd, m1);
        }
        /* positive floats: fp max == u32-bit max */
        unsigned bdb = __float_as_uint(bd);
        unsigned wv  = __reduce_max_sync(0xffffffffu, bdb);
        unsigned cand = 0xffffffffu;
        if (bdb == wv) {
#pragma unroll
            for (int j = 15; j >= 0; j--)
                if (__float_as_uint(mind[j]) == wv)
                    cand = (unsigned)(j*512 + tid);
        }
        unsigned wn = __reduce_min_sync(0xffffffffu, cand);
        int pb = (step & 1) * 16;
        if (lane == 0) { wbv[pb + wid] = wv; wbn[pb + wid] = wn; }
        __syncthreads();
        /* every warp reduces the 16 warp candidates (no 2nd barrier) */
        unsigned v  = wbv[pb + (lane & 15)];
        unsigned nn = wbn[pb + (lane & 15)];
        unsigned vm = __reduce_max_sync(0xffffffffu, v);
        unsigned c2 = (v == vm) ? nn : 0xffffffffu;
        unsigned win = __reduce_min_sync(0xffffffffu, c2);
        lx = sx[win]; ly = sy[win]; lz = sz[win];
        if (tid == 0) {
            g_centers[(b*3+0)*S_ + step] = lx;
            g_centers[(b*3+1)*S_ + step] = ly;
            g_centers[(b*3+2)*S_ + step] = lz;
        }
    }
}

/* ------------ ball query: warp per center ------------ */
#define BALL_SMEM (3*N_*4)
__global__ void __launch_bounds__(256) k_ball(const float* __restrict__ coords) {
    extern __shared__ float sm[];
    float* sx = sm; float* sy = sm + N_; float* sz = sm + 2*N_;
    int blk = blockIdx.x;
    int b = blk >> 5, part = blk & 31;
    int tid = threadIdx.x;
    const float* cb = coords + (size_t)b*3*N_;
    for (int n = tid; n < N_; n += 256) {
        sx[n] = cb[n]; sy[n] = cb[N_ + n]; sz[n] = cb[2*N_ + n];
    }
    __syncthreads();
    int w = tid >> 5, lane = tid & 31;
    for (int cc = 0; cc < 8; cc++) {
        int s = part*64 + w*8 + cc;
        float cx = g_centers[(b*3+0)*S_ + s];
        float cy = g_centers[(b*3+1)*S_ + s];
        float cz = g_centers[(b*3+2)*S_ + s];
        float cn = __fadd_rn(__fadd_rn(__fmul_rn(cx,cx), __fmul_rn(cy,cy)), __fmul_rn(cz,cz));
        int found = 0, firstn = 0;
        int* op = &g_nidx[((size_t)b*S_ + s)*KNB];
        for (int base = 0; base < N_; base += 32) {
            int n = base + lane;
            float x = sx[n], y = sy[n], z = sz[n];
            float pn = __fadd_rn(__fadd_rn(__fmul_rn(x,x), __fmul_rn(y,y)), __fmul_rn(z,z));
            float cp = __fadd_rn(__fadd_rn(__fmul_rn(cx,x), __fmul_rn(cy,y)), __fmul_rn(cz,z));
            float d2 = __fsub_rn(__fadd_rn(cn, pn), __fmul_rn(2.0f, cp));
            bool hit = d2 < 0.0625f;
            unsigned bal = __ballot_sync(0xffffffffu, hit);
            if (bal) {
                if (found == 0) firstn = base + __ffs(bal) - 1;
                int slot = found + __popc(bal & ((1u << lane) - 1u));
                if (hit && slot < KNB) op[slot] = n;
                found += __popc(bal);
                if (found >= KNB) break;
            }
        }
        if (found < KNB) {
            int fill = (found > 0) ? firstn : 0;
            for (int sl = found + lane; sl < KNB; sl += 32) op[sl] = fill;
        }
    }
}

/* ------------ conv0: gather + (67->64), 2 out-groups x 2 pts ------------ */
#define CONV0_SMEM (68*128*4 + 68*32*8 + 64*4)
__global__ void __launch_bounds__(128) k_conv0(const float* __restrict__ coords,
                                               const float* __restrict__ w0,
                                               const float* __restrict__ b0) {
    extern __shared__ float sm[];
    float* xs = sm;                       /* [68][128] */
    ull*   wp = (ull*)(sm + 68*128);      /* [68][32] packed out-pairs */
    float* bs = (float*)(wp + 68*32);
    int tid = threadIdx.x;
    int b = blockIdx.x >> 9;
    int pbase = (blockIdx.x & 511)*128;
    int p = pbase + tid;

    for (int k2 = tid; k2 < 68*32; k2 += 128) {
        int i = k2 >> 5, o2 = k2 & 31;
        float a = (i < 67) ? w0[(2*o2)*67 + i]   : 0.0f;
        float c = (i < 67) ? w0[(2*o2+1)*67 + i] : 0.0f;
        wp[k2] = pk2(a, c);
    }
    if (tid < 64) bs[tid] = b0[tid];

    int s = p >> 5;
    int n = g_nidx[((size_t)b*S_ + s)*KNB + (p & 31)];
    const float* cb = coords + (size_t)b*3*N_;
    xs[0*128 + tid] = __fsub_rn(cb[n],        g_centers[(b*3+0)*S_ + s]);
    xs[1*128 + tid] = __fsub_rn(cb[N_ + n],   g_centers[(b*3+1)*S_ + s]);
    xs[2*128 + tid] = __fsub_rn(cb[2*N_ + n], g_centers[(b*3+2)*S_ + s]);
    const float4* fp = (const float4*)(g_featT + ((size_t)b*N_ + n)*C_);
#pragma unroll
    for (int q = 0; q < 16; q++) {
        float4 v = fp[q]; int ib = 3 + 4*q;
        xs[(ib+0)*128 + tid] = v.x; xs[(ib+1)*128 + tid] = v.y;
        xs[(ib+2)*128 + tid] = v.z; xs[(ib+3)*128 + tid] = v.w;
    }
    xs[67*128 + tid] = 0.0f;
    __syncthreads();

    int og  = tid >> 6;            /* 0..1: outputs og*32..og*32+31 */
    int pt0 = (tid & 63) * 2;
    ull acc0[16], acc1[16];
#pragma unroll
    for (int q = 0; q < 16; q++) {
        ull bv = pk2(bs[og*32 + 2*q], bs[og*32 + 2*q + 1]);
        acc0[q] = bv; acc1[q] = bv;
    }
#pragma unroll 2
    for (int i = 0; i < 68; i++) {
        ull xv = *(const ull*)(xs + i*128 + pt0);
        float x0, x1; upk2(xv, x0, x1);
        ull xx0 = pk2(x0, x0), xx1 = pk2(x1, x1);
        const ulonglong2* wr = (const ulonglong2*)(wp + i*32 + og*16);
#pragma unroll
        for (int q = 0; q < 8; q++) {
            ulonglong2 wq = wr[q];
            acc0[2*q]   = fma2(wq.x, xx0, acc0[2*q]);
            acc1[2*q]   = fma2(wq.x, xx1, acc1[2*q]);
            acc0[2*q+1] = fma2(wq.y, xx0, acc0[2*q+1]);
            acc1[2*q+1] = fma2(wq.y, xx1, acc1[2*q+1]);
        }
    }
    float* yb = g_bufA + ((size_t)b*64)*PTS + pbase + pt0;
#pragma unroll
    for (int q = 0; q < 16; q++) {
        int o = og*32 + 2*q;
        float a00, a01, a10, a11;
        upk2(acc0[q], a00, a01);
        upk2(acc1[q], a10, a11);
        *(float2*)(yb + (size_t)o*PTS)     = make_float2(a00, a10);
        *(float2*)(yb + (size_t)(o+1)*PTS) = make_float2(a01, a11);
    }
}

/* ------------ per-(b,c) stats: deterministic two-stage ------------ */
template<int COUT, bool SRC_A>
__global__ void __launch_bounds__(256) k_stats(int off) {
    const float* y = SRC_A ? g_bufA : g_bufB;
    int bc = blockIdx.x;
    const float4* p4 = (const float4*)(y + (size_t)bc*PTS);
    float s = 0.0f, q = 0.0f;
    for (int i = threadIdx.x; i < PTS/4; i += 256) {
        float4 v = p4[i];
        s += v.x + v.y + v.z + v.w;
        q += v.x*v.x + v.y*v.y + v.z*v.z + v.w*v.w;
    }
    double ds = (double)s, dq = (double)q;
    int lane = threadIdx.x & 31, w = threadIdx.x >> 5;
#pragma unroll
    for (int o = 16; o; o >>= 1) {
        ds += __shfl_xor_sync(0xffffffffu, ds, o);
        dq += __shfl_xor_sync(0xffffffffu, dq, o);
    }
    __shared__ double sh[16];
    if (lane == 0) { sh[w] = ds; sh[8 + w] = dq; }
    __syncthreads();
    if (threadIdx.x == 0) {
        double S = 0.0, Q = 0.0;
#pragma unroll
        for (int i = 0; i < 8; i++) { S += sh[i]; Q += sh[8 + i]; }
        g_csum[off + bc] = S; g_csq[off + bc] = Q;
    }
}

/* ------------ convN64: GN + SiLU + (64->64), 2 out-groups x 2 pts ------------ */
#define CONVN64_SMEM (64*128*4 + 64*32*8 + (64+64+64)*4)
__global__ void __launch_bounds__(128) k_convN64(const float* __restrict__ w,
                                                 const float* __restrict__ bb,
                                                 const float* __restrict__ gamma,
                                                 const float* __restrict__ beta,
                                                 int off, double inv_cnt) {
    extern __shared__ float sm[];
    float* xs = sm;                        /* [64][128] */
    ull*   wp = (ull*)(sm + 64*128);       /* [64][32] */
    float* bs = (float*)(wp + 64*32);
    float* al = bs + 64;
    float* bt = al + 64;
    int tid = threadIdx.x;
    int b = blockIdx.x >> 9;
    int pbase = (blockIdx.x & 511)*128;
    int p = pbase + tid;

    for (int k2 = tid; k2 < 64*32; k2 += 128) {
        int i = k2 >> 5, o2 = k2 & 31;
        wp[k2] = pk2(w[(2*o2)*64 + i], w[(2*o2+1)*64 + i]);
    }
    if (tid < 64) bs[tid] = bb[tid];
    if (tid < 64) {
        int g = tid >> 3;
        double ms = 0.0, qs = 0.0;
#pragma unroll
        for (int cc = 0; cc < 8; cc++) {
            ms += g_csum[off + b*64 + g*8 + cc];
            qs += g_csq [off + b*64 + g*8 + cc];
        }
        double mu  = ms * inv_cnt;
        double var = qs * inv_cnt - mu*mu;
        float rstd = (float)rsqrt(var + 1e-5);
        float a = gamma[tid] * rstd;
        al[tid] = a;
        bt[tid] = beta[tid] - (float)mu * a;
    }
    __syncthreads();

#pragma unroll 1
    for (int ci = 0; ci < 64; ci++) {
        float v  = g_bufA[((size_t)b*64 + ci)*PTS + p];
        float xn = fmaf(v, al[ci], bt[ci]);
        float sg = __fdividef(1.0f, 1.0f + __expf(-xn));
        xs[ci*128 + tid] = xn * sg;
    }
    __syncthreads();

    int og  = tid >> 6;
    int pt0 = (tid & 63) * 2;
    ull acc0[16], acc1[16];
#pragma unroll
    for (int q = 0; q < 16; q++) {
        ull bv = pk2(bs[og*32 + 2*q], bs[og*32 + 2*q + 1]);
        acc0[q] = bv; acc1[q] = bv;
    }
#pragma unroll 2
    for (int i = 0; i < 64; i++) {
        ull xv = *(const ull*)(xs + i*128 + pt0);
        float x0, x1; upk2(xv, x0, x1);
        ull xx0 = pk2(x0, x0), xx1 = pk2(x1, x1);
        const ulonglong2* wr = (const ulonglong2*)(wp + i*32 + og*16);
#pragma unroll
        for (int q = 0; q < 8; q++) {
            ulonglong2 wq = wr[q];
            acc0[2*q]   = fma2(wq.x, xx0, acc0[2*q]);
            acc1[2*q]   = fma2(wq.x, xx1, acc1[2*q]);
            acc0[2*q+1] = fma2(wq.y, xx0, acc0[2*q+1]);
            acc1[2*q+1] = fma2(wq.y, xx1, acc1[2*q+1]);
        }
    }
    float* yb = g_bufB + ((size_t)b*64)*PTS + pbase + pt0;
#pragma unroll
    for (int q = 0; q < 16; q++) {
        int o = og*32 + 2*q;
        float a00, a01, a10, a11;
        upk2(acc0[q], a00, a01);
        upk2(acc1[q], a10, a11);
        *(float2*)(yb + (size_t)o*PTS)     = make_float2(a00, a10);
        *(float2*)(yb + (size_t)(o+1)*PTS) = make_float2(a01, a11);
    }
}

/* ------------ conv128: GN + SiLU + (64->128), 256 thr, 4 out-groups x 2 pts ------------ */
#define CONV128_SMEM (64*128*4 + 64*64*8 + (128+64+64)*4)
__global__ void __launch_bounds__(256) k_conv128(const float* __restrict__ w,
                                                 const float* __restrict__ bb,
                                                 const float* __restrict__ gamma,
                                                 const float* __restrict__ beta,
                                                 int off, double inv_cnt) {
    extern __shared__ float sm[];
    float* xs = sm;                        /* [64][128] */
    ull*   wp = (ull*)(sm + 64*128);       /* [64][64] out-pairs */
    float* bs = (float*)(wp + 64*64);      /* [128] */
    float* al = bs + 128;
    float* bt = al + 64;
    int tid = threadIdx.x;
    int b = blockIdx.x >> 9;
    int pbase = (blockIdx.x & 511)*128;

    for (int k2 = tid; k2 < 64*64; k2 += 256) {
        int i = k2 >> 6, o2 = k2 & 63;
        wp[k2] = pk2(w[(2*o2)*64 + i], w[(2*o2+1)*64 + i]);
    }
    if (tid < 128) bs[tid] = bb[tid];
    if (tid < 64) {
        int g = tid >> 3;
        double ms = 0.0, qs = 0.0;
#pragma unroll
        for (int cc = 0; cc < 8; cc++) {
            ms += g_csum[off + b*64 + g*8 + cc];
            qs += g_csq [off + b*64 + g*8 + cc];
        }
        double mu  = ms * inv_cnt;
        double var = qs * inv_cnt - mu*mu;
        float rstd = (float)rsqrt(var + 1e-5);
        float a = gamma[tid] * rstd;
        al[tid] = a;
        bt[tid] = beta[tid] - (float)mu * a;
    }
    __syncthreads();

    {
        int h = tid >> 7, pt = tid & 127;
        int p = pbase + pt;
#pragma unroll 1
        for (int cc = 0; cc < 32; cc++) {
            int ci = h*32 + cc;
            float v  = g_bufB[((size_t)b*64 + ci)*PTS + p];
            float xn = fmaf(v, al[ci], bt[ci]);
            float sg = __fdividef(1.0f, 1.0f + __expf(-xn));
            xs[ci*128 + pt] = xn * sg;
        }
    }
    __syncthreads();

    int og  = tid >> 6;            /* 0..3 */
    int pt0 = (tid & 63) * 2;
    ull acc0[16], acc1[16];
#pragma unroll
    for (int q = 0; q < 16; q++) {
        ull bv = pk2(bs[og*32 + 2*q], bs[og*32 + 2*q + 1]);
        acc0[q] = bv; acc1[q] = bv;
    }
#pragma unroll 2
    for (int i = 0; i < 64; i++) {
        ull xv = *(const ull*)(xs + i*128 + pt0);
        float x0, x1; upk2(xv, x0, x1);
        ull xx0 = pk2(x0, x0), xx1 = pk2(x1, x1);
        const ulonglong2* wr = (const ulonglong2*)(wp + i*64 + og*16);
#pragma unroll
        for (int q = 0; q < 8; q++) {
            ulonglong2 wq = wr[q];
            acc0[2*q]   = fma2(wq.x, xx0, acc0[2*q]);
            acc1[2*q]   = fma2(wq.x, xx1, acc1[2*q]);
            acc0[2*q+1] = fma2(wq.y, xx0, acc0[2*q+1]);
            acc1[2*q+1] = fma2(wq.y, xx1, acc1[2*q+1]);
        }
    }
    float* yb = g_bufA + ((size_t)b*128)*PTS + pbase + pt0;
#pragma unroll
    for (int q = 0; q < 16; q++) {
        int o = og*32 + 2*q;
        float a00, a01, a10, a11;
        upk2(acc0[q], a00, a01);
        upk2(acc1[q], a10, a11);
        *(float2*)(yb + (size_t)o*PTS)     = make_float2(a00, a10);
        *(float2*)(yb + (size_t)(o+1)*PTS) = make_float2(a01, a11);
    }
}

/* ------------ final: GN + SiLU + max over K ------------ */
__global__ void __launch_bounds__(256) k_final(const float* __restrict__ gamma,
                                               const float* __restrict__ beta,
                                               float* __restrict__ out,
                                               int off, double inv_cnt) {
    int blk = blockIdx.x;
    int bc = blk >> 5;
    int chunk = blk & 31;
    int b = bc >> 7, c = bc & 127;
    __shared__ float s_a, s_b;
    if (threadIdx.x == 0) {
        int g = c >> 4;
        double ms = 0.0, qs = 0.0;
#pragma unroll
        for (int cc = 0; cc < 16; cc++) {
            ms += g_csum[off + b*128 + g*16 + cc];
            qs += g_csq [off + b*128 + g*16 + cc];
        }
        double mu  = ms * inv_cnt;
        double var = qs * inv_cnt - mu*mu;
        float rstd = (float)rsqrt(var + 1e-5);
        float a = gamma[c] * rstd;
        s_a = a;
        s_b = beta[c] - (float)mu * a;
    }
    __syncthreads();
    float a = s_a, bt = s_b;
    int w = threadIdx.x >> 5, lane = threadIdx.x & 31;
    const float* base = g_bufA + (size_t)bc*PTS;
#pragma unroll 1
    for (int j = 0; j < 8; j++) {
        int s = chunk*64 + w*8 + j;
        float v  = base[s*32 + lane];
        float xn = fmaf(v, a, bt);
        float sg = __fdividef(1.0f, 1.0f + __expf(-xn));
        float val = xn * sg;
#pragma unroll
        for (int o = 16; o; o >>= 1)
            val = fmaxf(val, __shfl_xor_sync(0xffffffffu, val, o));
        if (lane == 0) out[(size_t)bc*S_ + s] = val;
    }
}

extern "C" void kernel_launch(void* const* d_in, const int* in_sizes, int n_in,
                              void* d_out, int out_size) {
    const float* coords   = (const float*)d_in[0];
    const float* features = (const float*)d_in[1];
    const float* w0 = (const float*)d_in[2];
    const float* b0 = (const float*)d_in[3];
    const float* g0 = (const float*)d_in[4];
    const float* be0= (const float*)d_in[5];
    const float* w1 = (const float*)d_in[6];
    const float* b1 = (const float*)d_in[7];
    const float* g1 = (const float*)d_in[8];
    const float* be1= (const float*)d_in[9];
    const float* w2 = (const float*)d_in[10];
    const float* b2 = (const float*)d_in[11];
    const float* g2 = (const float*)d_in[12];
    const float* be2= (const float*)d_in[13];
    float* out = (float*)d_out;

    cudaFuncSetAttribute(k_fps,     cudaFuncAttributeMaxDynamicSharedMemorySize, FPS_SMEM);
    cudaFuncSetAttribute(k_ball,    cudaFuncAttributeMaxDynamicSharedMemorySize, BALL_SMEM);
    cudaFuncSetAttribute(k_conv0,   cudaFuncAttributeMaxDynamicSharedMemorySize, CONV0_SMEM);
    cudaFuncSetAttribute(k_convN64, cudaFuncAttributeMaxDynamicSharedMemorySize, CONVN64_SMEM);
    cudaFuncSetAttribute(k_conv128, cudaFuncAttributeMaxDynamicSharedMemorySize, CONV128_SMEM);

    dim3 tg(N_/32, C_/32, B_);
    k_transpose<<<tg, dim3(32,8)>>>(features);
    k_fps<<<B_, 512, FPS_SMEM>>>(coords);
    k_ball<<<B_*32, 256, BALL_SMEM>>>(coords);
    k_conv0<<<B_*512, 128, CONV0_SMEM>>>(coords, w0, b0);
    k_stats<64,true><<<B_*64, 256>>>(0);
    k_convN64<<<B_*512, 128, CONVN64_SMEM>>>(w1, b1, g0, be0, 0, 1.0/(8.0*PTS));
    k_stats<64,false><<<B_*64, 256>>>(512);
    k_conv128<<<B_*512, 256, CONV128_SMEM>>>(w2, b2, g1, be1, 512, 1.0/(8.0*PTS));
    k_stats<128,true><<<B_*128, 256>>>(1024);
    k_final<<<B_*128*32, 256>>>(g2, be2, out, 1024, 1.0/(16.0*PTS));
}